// round 9
// baseline (speedup 1.0000x reference)
#include <cuda_runtime.h>
#include <cuda_fp16.h>

#define NN   100000           // nodes
#define NE   20000            // hyperedges
#define D    128              // feature dim
#define NTOT (NN + NE)
#define CAP_N 64              // node bucket capacity  (Poisson(8):  overflow ~0)
#define CAP_E 128             // edge bucket capacity  (Poisson(40): overflow ~0)

typedef unsigned long long u64;

// ---- scratch (static device globals; no allocation allowed) ----
__device__ int      g_cur[NTOT];              // [0,NN): node cursors ; [NN,NTOT): edge cursors
__device__ float    g_se[NE];                 // (sum invdn over edge)/d_e
__device__ int      g_nlist[NN * CAP_N];      // node -> edge ids (strided buckets)
__device__ int      g_elist[NE * CAP_E];      // edge -> node ids (strided buckets)
__device__ __half2  g_xh2[NN * (D / 2)];      // x in fp16 (25.6 MB)
__device__ float4   g_eraw4[NE * (D / 4)];    // gathered edge feats fp32 (10.2 MB)
__device__ __half2  g_ewh2[NE * (D / 2)];     // e_raw @ W^T in fp16 (5.1 MB)
__device__ float4   g_wt4[D * D / 4];         // W^T (k-major)

__device__ __forceinline__ u64 dup2(float f) {
    unsigned int u = __float_as_uint(f);
    return ((u64)u << 32) | (u64)u;
}
#define FMA2(d, a, b) \
    asm("fma.rn.f32x2 %0, %1, %2, %0;" : "+l"(d) : "l"(a), "l"(b))
#define UNPACK2(lo, hi, v) \
    asm("mov.b64 {%0,%1}, %2;" : "=r"(lo), "=r"(hi) : "l"(v))

// ------------------------------------------------------------------
// combined fill: strided buckets; cursor == degree when done.
// 4 incidences per thread -> 8 independent ATOMG chains in flight.
// ------------------------------------------------------------------
__global__ void k_fill(const int2* __restrict__ ni2, const int2* __restrict__ ei2,
                       int npair) {
    int i = (blockIdx.x * blockDim.x + threadIdx.x) * 2;
    if (i >= npair) return;
    int2 na = __ldg(&ni2[i]);
    int2 ea = __ldg(&ei2[i]);
    bool two = (i + 1 < npair);
    int2 nb = two ? __ldg(&ni2[i + 1]) : make_int2(0, 0);
    int2 eb = two ? __ldg(&ei2[i + 1]) : make_int2(0, 0);

    int p0 = atomicAdd(&g_cur[NN + ea.x], 1);
    int p1 = atomicAdd(&g_cur[NN + ea.y], 1);
    int q0 = atomicAdd(&g_cur[na.x], 1);
    int q1 = atomicAdd(&g_cur[na.y], 1);
    int p2 = 0, p3 = 0, q2 = 0, q3 = 0;
    if (two) {
        p2 = atomicAdd(&g_cur[NN + eb.x], 1);
        p3 = atomicAdd(&g_cur[NN + eb.y], 1);
        q2 = atomicAdd(&g_cur[nb.x], 1);
        q3 = atomicAdd(&g_cur[nb.y], 1);
    }
    if (p0 < CAP_E) g_elist[ea.x * CAP_E + p0] = na.x;
    if (p1 < CAP_E) g_elist[ea.y * CAP_E + p1] = na.y;
    if (q0 < CAP_N) g_nlist[na.x * CAP_N + q0] = ea.x;
    if (q1 < CAP_N) g_nlist[na.y * CAP_N + q1] = ea.y;
    if (two) {
        if (p2 < CAP_E) g_elist[eb.x * CAP_E + p2] = nb.x;
        if (p3 < CAP_E) g_elist[eb.y * CAP_E + p3] = nb.y;
        if (q2 < CAP_N) g_nlist[nb.x * CAP_N + q2] = eb.x;
        if (q3 < CAP_N) g_nlist[nb.y * CAP_N + q3] = eb.y;
    }
}

// ------------------------------------------------------------------
// x (fp32) -> fp16
// ------------------------------------------------------------------
__global__ void k_xh(const float4* __restrict__ x4) {
    int i = blockIdx.x * blockDim.x + threadIdx.x;
    if (i < NN * 32) {
        float4 v = __ldg(&x4[i]);
        __half2 h0 = __float22half2_rn(make_float2(v.x, v.y));
        __half2 h1 = __float22half2_rn(make_float2(v.z, v.w));
        uint2 pk;
        pk.x = *reinterpret_cast<unsigned int*>(&h0);
        pk.y = *reinterpret_cast<unsigned int*>(&h1);
        reinterpret_cast<uint2*>(g_xh2)[i] = pk;
    }
}

// ------------------------------------------------------------------
// W (out,in) -> W^T (k-major)
// ------------------------------------------------------------------
__global__ void k_transpose(const float* __restrict__ W) {
    __shared__ float tile[32][33];
    int b = blockIdx.x;
    int bx = b & 3, by = b >> 2;
    int tx = threadIdx.x & 31, ty = threadIdx.x >> 5;
    float* wt = (float*)g_wt4;
#pragma unroll
    for (int j = 0; j < 32; j += 8)
        tile[ty + j][tx] = W[(by * 32 + ty + j) * D + bx * 32 + tx];
    __syncthreads();
#pragma unroll
    for (int j = 0; j < 32; j += 8)
        wt[(bx * 32 + ty + j) * D + by * 32 + tx] = tile[tx][ty + j];
}

// ------------------------------------------------------------------
// sc1: nodes -> hyperedges gather (fp16 x). warp per edge.
// Uniform predicated MLP-8: no remainder loop; invalid elements get
// sv=0 (one SEL each) and a clamped-safe index.
// ------------------------------------------------------------------
__global__ void k_sc1g(int e0, int e1) {
    int e    = e0 + ((blockIdx.x * blockDim.x + threadIdx.x) >> 5);
    int lane = threadIdx.x & 31;
    if (e >= e1) return;
    int off = e * CAP_E;
    int cnt = min(__ldg(&g_cur[NN + e]), CAP_E);
    const uint2* xh = (const uint2*)g_xh2;
    float4 a = make_float4(0.f, 0.f, 0.f, 0.f);
    float se = 0.f;
    for (int j = 0; j < cnt; j += 8) {
        int idx[8];
#pragma unroll
        for (int u = 0; u < 8; ++u) {
            int raw = __ldg(&g_elist[off + min(j + u, cnt - 1)]);
            idx[u] = (int)min((unsigned)raw, (unsigned)(NN - 1));   // clamp-safe
        }
        float sv[8];
#pragma unroll
        for (int u = 0; u < 8; ++u) {
            float s = rsqrtf((float)__ldg(&g_cur[idx[u]]));
            sv[u] = (j + u < cnt) ? s : 0.f;
        }
        uint2 rv[8];
#pragma unroll
        for (int u = 0; u < 8; ++u) rv[u] = __ldg(&xh[idx[u] * 32 + lane]);
#pragma unroll
        for (int u = 0; u < 8; ++u) {
            float2 f0 = __half22float2(*reinterpret_cast<__half2*>(&rv[u].x));
            float2 f1 = __half22float2(*reinterpret_cast<__half2*>(&rv[u].y));
            a.x += f0.x * sv[u]; a.y += f0.y * sv[u];
            a.z += f1.x * sv[u]; a.w += f1.y * sv[u];
            se  += sv[u];
        }
    }
    float ide = (cnt > 0) ? __fdividef(1.f, (float)cnt) : 0.f;
    a.x *= ide; a.y *= ide; a.z *= ide; a.w *= ide;
    g_eraw4[e * 32 + lane] = a;
    if (lane == 0) g_se[e] = se * ide;
}

// ------------------------------------------------------------------
// GEMM on edge-row range: g_ewh = half(g_eraw @ W^T)
// ------------------------------------------------------------------
__global__ void __launch_bounds__(256, 2) k_gemm(int row0, int row1) {
    __shared__ u64 sW[128 * 64];
    __shared__ u64 sx[64 * 32];

    const int t  = threadIdx.x;
    const int r0 = row0 + blockIdx.x * 64;
    const int cg = t & 15;
    const int rg = t >> 4;

    {
        const ulonglong2* src = (const ulonglong2*)g_wt4;
        ulonglong2* dst = (ulonglong2*)sW;
        for (int i = t; i < 4096; i += 256) dst[i] = src[i];
    }

    u64 acc[4][4];
#pragma unroll
    for (int r = 0; r < 4; ++r)
#pragma unroll
        for (int p = 0; p < 4; ++p) acc[r][p] = 0ull;

    for (int kc = 0; kc < 4; ++kc) {
        for (int i = t; i < 512; i += 256) {
            int row = i >> 3, c4 = i & 7;
            int gr = r0 + row;
            float4 v = (gr < row1) ? g_eraw4[gr * 32 + kc * 8 + c4]
                                   : make_float4(0.f, 0.f, 0.f, 0.f);
            u64* dst = &sx[row * 32 + c4 * 4];
            dst[0] = dup2(v.x); dst[1] = dup2(v.y);
            dst[2] = dup2(v.z); dst[3] = dup2(v.w);
        }
        __syncthreads();

#pragma unroll
        for (int kk = 0; kk < 32; ++kk) {
            const ulonglong2* wp = (const ulonglong2*)&sW[(kc * 32 + kk) * 64 + cg * 4];
            ulonglong2 wa = wp[0], wb = wp[1];
            u64 w0 = wa.x, w1 = wa.y, w2 = wb.x, w3 = wb.y;
#pragma unroll
            for (int r = 0; r < 4; ++r) {
                u64 xv = sx[(rg * 4 + r) * 32 + kk];
                FMA2(acc[r][0], xv, w0);
                FMA2(acc[r][1], xv, w1);
                FMA2(acc[r][2], xv, w2);
                FMA2(acc[r][3], xv, w3);
            }
        }
        __syncthreads();
    }

#pragma unroll
    for (int r = 0; r < 4; ++r) {
        int gr = r0 + rg * 4 + r;
        if (gr < row1) {
            unsigned int lo[4], hi[4];
            UNPACK2(lo[0], hi[0], acc[r][0]); UNPACK2(lo[1], hi[1], acc[r][1]);
            UNPACK2(lo[2], hi[2], acc[r][2]); UNPACK2(lo[3], hi[3], acc[r][3]);
            uint4 pk;
            __half2 h;
            h = __float22half2_rn(make_float2(__uint_as_float(lo[0]), __uint_as_float(hi[0])));
            pk.x = *reinterpret_cast<unsigned int*>(&h);
            h = __float22half2_rn(make_float2(__uint_as_float(lo[1]), __uint_as_float(hi[1])));
            pk.y = *reinterpret_cast<unsigned int*>(&h);
            h = __float22half2_rn(make_float2(__uint_as_float(lo[2]), __uint_as_float(hi[2])));
            pk.z = *reinterpret_cast<unsigned int*>(&h);
            h = __float22half2_rn(make_float2(__uint_as_float(lo[3]), __uint_as_float(hi[3])));
            pk.w = *reinterpret_cast<unsigned int*>(&h);
            reinterpret_cast<uint4*>(g_ewh2)[gr * 16 + cg] = pk;
        }
    }
}

// ------------------------------------------------------------------
// sc2: hyperedges -> nodes gather (fp16 ew). warp per node.
// Uniform predicated MLP-8 (critical: ~45% of nodes have cnt<8).
// ------------------------------------------------------------------
__global__ void k_sc2g(const float* __restrict__ bias, float4* __restrict__ out4) {
    int n    = (blockIdx.x * blockDim.x + threadIdx.x) >> 5;
    int lane = threadIdx.x & 31;
    if (n >= NN) return;
    int off  = n * CAP_N;
    int rawc = __ldg(&g_cur[n]);
    int cnt  = min(rawc, CAP_N);
    const uint2* ewh = (const uint2*)g_ewh2;
    float4 a = make_float4(0.f, 0.f, 0.f, 0.f);
    float ts = 0.f;
    for (int j = 0; j < cnt; j += 8) {
        int idx[8];
        float m[8];
#pragma unroll
        for (int u = 0; u < 8; ++u) {
            int raw = __ldg(&g_nlist[off + min(j + u, cnt - 1)]);
            idx[u] = (int)min((unsigned)raw, (unsigned)(NE - 1));
            m[u] = (j + u < cnt) ? 1.f : 0.f;
        }
        uint2 rv[8];
#pragma unroll
        for (int u = 0; u < 8; ++u) rv[u] = __ldg(&ewh[idx[u] * 32 + lane]);
#pragma unroll
        for (int u = 0; u < 8; ++u) {
            ts += m[u] * __ldg(&g_se[idx[u]]);
            float2 f0 = __half22float2(*reinterpret_cast<__half2*>(&rv[u].x));
            float2 f1 = __half22float2(*reinterpret_cast<__half2*>(&rv[u].y));
            a.x += f0.x * m[u]; a.y += f0.y * m[u];
            a.z += f1.x * m[u]; a.w += f1.y * m[u];
        }
    }
    float s = (cnt > 0) ? rsqrtf((float)rawc) : 0.f;
    float4 bv = __ldg(&((const float4*)bias)[lane]);
    float4 o;
    o.x = fmaxf(s * (a.x + ts * bv.x), 0.f);
    o.y = fmaxf(s * (a.y + ts * bv.y), 0.f);
    o.z = fmaxf(s * (a.z + ts * bv.z), 0.f);
    o.w = fmaxf(s * (a.w + ts * bv.w), 0.f);
    out4[n * 32 + lane] = o;
}

// ------------------------------------------------------------------
extern "C" void kernel_launch(void* const* d_in, const int* in_sizes, int n_in,
                              void* d_out, int out_size) {
    const float4* x4   = (const float4*)d_in[0];
    const float*  W    = (const float*) d_in[1];
    const float*  bias = (const float*) d_in[2];
    const int*    ni   = (const int*)   d_in[3];
    const int*    ei   = (const int*)   d_in[4];
    const int     ninc = in_sizes[3];
    float4* out4 = (float4*)d_out;

    cudaStream_t side;
    cudaEvent_t evFork, evPre, evC[4], evG;
    cudaStreamCreateWithFlags(&side, cudaStreamNonBlocking);
    cudaEventCreateWithFlags(&evFork, cudaEventDisableTiming);
    cudaEventCreateWithFlags(&evPre,  cudaEventDisableTiming);
    for (int c = 0; c < 4; ++c) cudaEventCreateWithFlags(&evC[c], cudaEventDisableTiming);
    cudaEventCreateWithFlags(&evG, cudaEventDisableTiming);

    void* curp = nullptr;
    cudaGetSymbolAddress(&curp, g_cur);

    const int npair = ninc / 2;
    const int nth = (npair + 1) / 2;   // 4 incidences per thread
    const int CH = NE / 4;             // 4 edge chunks

    // main: cursors -> combined fill
    cudaMemsetAsync(curp, 0, NTOT * sizeof(int), 0);

    // side: transpose + x->half (hidden under memset+fill)
    cudaEventRecord(evFork, 0);
    cudaStreamWaitEvent(side, evFork, 0);
    k_transpose<<<16, 256, 0, side>>>(W);
    k_xh<<<(NN * 32 + 255) / 256, 256, 0, side>>>(x4);
    cudaEventRecord(evPre, side);

    k_fill<<<(nth + 255) / 256, 256>>>((const int2*)ni, (const int2*)ei, npair);

    // main needs x_h from side
    cudaStreamWaitEvent(0, evPre, 0);

    // 4-way pipelined sc1 (main) / gemm (side)
    for (int c = 0; c < 4; ++c) {
        int lo = c * CH, hi = (c == 3) ? NE : (c + 1) * CH;
        k_sc1g<<<((hi - lo) * 32 + 255) / 256, 256>>>(lo, hi);
        cudaEventRecord(evC[c], 0);
        cudaStreamWaitEvent(side, evC[c], 0);
        k_gemm<<<(hi - lo + 63) / 64, 256, 0, side>>>(lo, hi);
    }
    cudaEventRecord(evG, side);

    cudaStreamWaitEvent(0, evG, 0);
    k_sc2g<<<(NN * 32 + 255) / 256, 256>>>(bias, out4);
}

// round 10
// speedup vs baseline: 1.1149x; 1.1149x over previous
#include <cuda_runtime.h>
#include <cuda_fp16.h>

#define NN   100000           // nodes
#define NE   20000            // hyperedges
#define D    128              // feature dim
#define NTOT (NN + NE)
#define CAP_N 64              // node bucket capacity  (Poisson(8):  overflow ~0)
#define CAP_E 128             // edge bucket capacity  (Poisson(40): overflow ~0)

typedef unsigned long long u64;

// ---- scratch (static device globals; no allocation allowed) ----
__device__ int      g_cur[NTOT];              // [0,NN): node cursors ; [NN,NTOT): edge cursors
__device__ float    g_se[NE];                 // (sum invdn over edge)/d_e
__device__ int      g_nlist[NN * CAP_N];      // node -> edge ids (strided buckets)
__device__ int      g_elist[NE * CAP_E];      // edge -> node ids (strided buckets)
__device__ __half2  g_xh2[NN * (D / 2)];      // x in fp16 (25.6 MB)
__device__ float4   g_eraw4[NE * (D / 4)];    // gathered edge feats fp32 (10.2 MB)
__device__ __half2  g_ewh2[NE * (D / 2)];     // e_raw @ W^T in fp16 (5.1 MB)
__device__ float4   g_wt4[D * D / 4];         // W^T (k-major)

__device__ __forceinline__ u64 dup2(float f) {
    unsigned int u = __float_as_uint(f);
    return ((u64)u << 32) | (u64)u;
}
#define FMA2(d, a, b) \
    asm("fma.rn.f32x2 %0, %1, %2, %0;" : "+l"(d) : "l"(a), "l"(b))
#define UNPACK2(lo, hi, v) \
    asm("mov.b64 {%0,%1}, %2;" : "=r"(lo), "=r"(hi) : "l"(v))

// ------------------------------------------------------------------
// combined fill: strided buckets; cursor == degree when done.
// 4 incidences per thread -> 8 independent ATOMG chains in flight.
// ------------------------------------------------------------------
__global__ void k_fill(const int2* __restrict__ ni2, const int2* __restrict__ ei2,
                       int npair) {
    int i = (blockIdx.x * blockDim.x + threadIdx.x) * 2;
    if (i >= npair) return;
    int2 na = __ldg(&ni2[i]);
    int2 ea = __ldg(&ei2[i]);
    bool two = (i + 1 < npair);
    int2 nb = two ? __ldg(&ni2[i + 1]) : make_int2(0, 0);
    int2 eb = two ? __ldg(&ei2[i + 1]) : make_int2(0, 0);

    int p0 = atomicAdd(&g_cur[NN + ea.x], 1);
    int p1 = atomicAdd(&g_cur[NN + ea.y], 1);
    int q0 = atomicAdd(&g_cur[na.x], 1);
    int q1 = atomicAdd(&g_cur[na.y], 1);
    int p2 = 0, p3 = 0, q2 = 0, q3 = 0;
    if (two) {
        p2 = atomicAdd(&g_cur[NN + eb.x], 1);
        p3 = atomicAdd(&g_cur[NN + eb.y], 1);
        q2 = atomicAdd(&g_cur[nb.x], 1);
        q3 = atomicAdd(&g_cur[nb.y], 1);
    }
    if (p0 < CAP_E) g_elist[ea.x * CAP_E + p0] = na.x;
    if (p1 < CAP_E) g_elist[ea.y * CAP_E + p1] = na.y;
    if (q0 < CAP_N) g_nlist[na.x * CAP_N + q0] = ea.x;
    if (q1 < CAP_N) g_nlist[na.y * CAP_N + q1] = ea.y;
    if (two) {
        if (p2 < CAP_E) g_elist[eb.x * CAP_E + p2] = nb.x;
        if (p3 < CAP_E) g_elist[eb.y * CAP_E + p3] = nb.y;
        if (q2 < CAP_N) g_nlist[nb.x * CAP_N + q2] = eb.x;
        if (q3 < CAP_N) g_nlist[nb.y * CAP_N + q3] = eb.y;
    }
}

// ------------------------------------------------------------------
// x (fp32) -> fp16
// ------------------------------------------------------------------
__global__ void k_xh(const float4* __restrict__ x4) {
    int i = blockIdx.x * blockDim.x + threadIdx.x;
    if (i < NN * 32) {
        float4 v = __ldg(&x4[i]);
        __half2 h0 = __float22half2_rn(make_float2(v.x, v.y));
        __half2 h1 = __float22half2_rn(make_float2(v.z, v.w));
        uint2 pk;
        pk.x = *reinterpret_cast<unsigned int*>(&h0);
        pk.y = *reinterpret_cast<unsigned int*>(&h1);
        reinterpret_cast<uint2*>(g_xh2)[i] = pk;
    }
}

// ------------------------------------------------------------------
// W (out,in) -> W^T (k-major)
// ------------------------------------------------------------------
__global__ void k_transpose(const float* __restrict__ W) {
    __shared__ float tile[32][33];
    int b = blockIdx.x;
    int bx = b & 3, by = b >> 2;
    int tx = threadIdx.x & 31, ty = threadIdx.x >> 5;
    float* wt = (float*)g_wt4;
#pragma unroll
    for (int j = 0; j < 32; j += 8)
        tile[ty + j][tx] = W[(by * 32 + ty + j) * D + bx * 32 + tx];
    __syncthreads();
#pragma unroll
    for (int j = 0; j < 32; j += 8)
        wt[(bx * 32 + ty + j) * D + by * 32 + tx] = tile[tx][ty + j];
}

// ------------------------------------------------------------------
// sc1: nodes -> hyperedges gather (fp16 x). warp per edge, MLP-8.
// (R7 version: plain unrolled loop + scalar remainder; Poisson(40)
//  means the tail is ~10% of work — not worth predication overhead.)
// ------------------------------------------------------------------
__global__ void k_sc1g(int e0, int e1) {
    int e    = e0 + ((blockIdx.x * blockDim.x + threadIdx.x) >> 5);
    int lane = threadIdx.x & 31;
    if (e >= e1) return;
    int off = e * CAP_E;
    int rawc = __ldg(&g_cur[NN + e]);
    int cnt  = min(rawc, CAP_E);
    const uint2* xh = (const uint2*)g_xh2;
    float4 a = make_float4(0.f, 0.f, 0.f, 0.f);
    float se = 0.f;
    int j = 0;
    for (; j + 8 <= cnt; j += 8) {
        int idx[8];
#pragma unroll
        for (int u = 0; u < 8; ++u) idx[u] = __ldg(&g_elist[off + j + u]);
        float sv[8];
#pragma unroll
        for (int u = 0; u < 8; ++u) sv[u] = rsqrtf((float)__ldg(&g_cur[idx[u]]));
        uint2 rv[8];
#pragma unroll
        for (int u = 0; u < 8; ++u) rv[u] = __ldg(&xh[idx[u] * 32 + lane]);
#pragma unroll
        for (int u = 0; u < 8; ++u) {
            float2 f0 = __half22float2(*reinterpret_cast<__half2*>(&rv[u].x));
            float2 f1 = __half22float2(*reinterpret_cast<__half2*>(&rv[u].y));
            a.x += f0.x * sv[u]; a.y += f0.y * sv[u];
            a.z += f1.x * sv[u]; a.w += f1.y * sv[u];
            se  += sv[u];
        }
    }
    for (; j < cnt; ++j) {
        int n = __ldg(&g_elist[off + j]);
        float s = rsqrtf((float)__ldg(&g_cur[n]));
        uint2 r = __ldg(&xh[n * 32 + lane]);
        float2 f0 = __half22float2(*reinterpret_cast<__half2*>(&r.x));
        float2 f1 = __half22float2(*reinterpret_cast<__half2*>(&r.y));
        a.x += f0.x * s; a.y += f0.y * s; a.z += f1.x * s; a.w += f1.y * s;
        se  += s;
    }
    float ide = (cnt > 0) ? __fdividef(1.f, (float)cnt) : 0.f;
    a.x *= ide; a.y *= ide; a.z *= ide; a.w *= ide;
    g_eraw4[e * 32 + lane] = a;
    if (lane == 0) g_se[e] = se * ide;
}

// ------------------------------------------------------------------
// GEMM on edge-row range: g_ewh = half(g_eraw @ W^T)
// packed fp32x2 FMA; 256 thr; tile 64x128; thread 4x8
// ------------------------------------------------------------------
__global__ void __launch_bounds__(256, 2) k_gemm(int row0, int row1) {
    __shared__ u64 sW[128 * 64];
    __shared__ u64 sx[64 * 32];

    const int t  = threadIdx.x;
    const int r0 = row0 + blockIdx.x * 64;
    const int cg = t & 15;
    const int rg = t >> 4;

    {
        const ulonglong2* src = (const ulonglong2*)g_wt4;
        ulonglong2* dst = (ulonglong2*)sW;
        for (int i = t; i < 4096; i += 256) dst[i] = src[i];
    }

    u64 acc[4][4];
#pragma unroll
    for (int r = 0; r < 4; ++r)
#pragma unroll
        for (int p = 0; p < 4; ++p) acc[r][p] = 0ull;

    for (int kc = 0; kc < 4; ++kc) {
        for (int i = t; i < 512; i += 256) {
            int row = i >> 3, c4 = i & 7;
            int gr = r0 + row;
            float4 v = (gr < row1) ? g_eraw4[gr * 32 + kc * 8 + c4]
                                   : make_float4(0.f, 0.f, 0.f, 0.f);
            u64* dst = &sx[row * 32 + c4 * 4];
            dst[0] = dup2(v.x); dst[1] = dup2(v.y);
            dst[2] = dup2(v.z); dst[3] = dup2(v.w);
        }
        __syncthreads();

#pragma unroll
        for (int kk = 0; kk < 32; ++kk) {
            const ulonglong2* wp = (const ulonglong2*)&sW[(kc * 32 + kk) * 64 + cg * 4];
            ulonglong2 wa = wp[0], wb = wp[1];
            u64 w0 = wa.x, w1 = wa.y, w2 = wb.x, w3 = wb.y;
#pragma unroll
            for (int r = 0; r < 4; ++r) {
                u64 xv = sx[(rg * 4 + r) * 32 + kk];
                FMA2(acc[r][0], xv, w0);
                FMA2(acc[r][1], xv, w1);
                FMA2(acc[r][2], xv, w2);
                FMA2(acc[r][3], xv, w3);
            }
        }
        __syncthreads();
    }

#pragma unroll
    for (int r = 0; r < 4; ++r) {
        int gr = r0 + rg * 4 + r;
        if (gr < row1) {
            unsigned int lo[4], hi[4];
            UNPACK2(lo[0], hi[0], acc[r][0]); UNPACK2(lo[1], hi[1], acc[r][1]);
            UNPACK2(lo[2], hi[2], acc[r][2]); UNPACK2(lo[3], hi[3], acc[r][3]);
            uint4 pk;
            __half2 h;
            h = __float22half2_rn(make_float2(__uint_as_float(lo[0]), __uint_as_float(hi[0])));
            pk.x = *reinterpret_cast<unsigned int*>(&h);
            h = __float22half2_rn(make_float2(__uint_as_float(lo[1]), __uint_as_float(hi[1])));
            pk.y = *reinterpret_cast<unsigned int*>(&h);
            h = __float22half2_rn(make_float2(__uint_as_float(lo[2]), __uint_as_float(hi[2])));
            pk.z = *reinterpret_cast<unsigned int*>(&h);
            h = __float22half2_rn(make_float2(__uint_as_float(lo[3]), __uint_as_float(hi[3])));
            pk.w = *reinterpret_cast<unsigned int*>(&h);
            reinterpret_cast<uint4*>(g_ewh2)[gr * 16 + cg] = pk;
        }
    }
}

// ------------------------------------------------------------------
// sc2: hyperedges -> nodes gather (fp16 ew). warp per node.
// Uniform predicated MLP-8: Poisson(8) means ~45% of nodes previously
// ran only the serial remainder — now every node gets MLP-8.
// ------------------------------------------------------------------
__global__ void k_sc2g(const float* __restrict__ bias, float4* __restrict__ out4) {
    int n    = (blockIdx.x * blockDim.x + threadIdx.x) >> 5;
    int lane = threadIdx.x & 31;
    if (n >= NN) return;
    int off  = n * CAP_N;
    int rawc = __ldg(&g_cur[n]);
    int cnt  = min(rawc, CAP_N);
    const uint2* ewh = (const uint2*)g_ewh2;
    float4 a = make_float4(0.f, 0.f, 0.f, 0.f);
    float ts = 0.f;
    for (int j = 0; j < cnt; j += 8) {
        int idx[8];
        float m[8];
#pragma unroll
        for (int u = 0; u < 8; ++u) {
            int raw = __ldg(&g_nlist[off + min(j + u, cnt - 1)]);
            idx[u] = (int)min((unsigned)raw, (unsigned)(NE - 1));
            m[u] = (j + u < cnt) ? 1.f : 0.f;
        }
        uint2 rv[8];
#pragma unroll
        for (int u = 0; u < 8; ++u) rv[u] = __ldg(&ewh[idx[u] * 32 + lane]);
#pragma unroll
        for (int u = 0; u < 8; ++u) {
            ts += m[u] * __ldg(&g_se[idx[u]]);
            float2 f0 = __half22float2(*reinterpret_cast<__half2*>(&rv[u].x));
            float2 f1 = __half22float2(*reinterpret_cast<__half2*>(&rv[u].y));
            a.x += f0.x * m[u]; a.y += f0.y * m[u];
            a.z += f1.x * m[u]; a.w += f1.y * m[u];
        }
    }
    float s = (cnt > 0) ? rsqrtf((float)rawc) : 0.f;
    float4 bv = __ldg(&((const float4*)bias)[lane]);
    float4 o;
    o.x = fmaxf(s * (a.x + ts * bv.x), 0.f);
    o.y = fmaxf(s * (a.y + ts * bv.y), 0.f);
    o.z = fmaxf(s * (a.z + ts * bv.z), 0.f);
    o.w = fmaxf(s * (a.w + ts * bv.w), 0.f);
    out4[n * 32 + lane] = o;
}

// ------------------------------------------------------------------
extern "C" void kernel_launch(void* const* d_in, const int* in_sizes, int n_in,
                              void* d_out, int out_size) {
    const float4* x4   = (const float4*)d_in[0];
    const float*  W    = (const float*) d_in[1];
    const float*  bias = (const float*) d_in[2];
    const int*    ni   = (const int*)   d_in[3];
    const int*    ei   = (const int*)   d_in[4];
    const int     ninc = in_sizes[3];
    float4* out4 = (float4*)d_out;

    cudaStream_t side;
    cudaEvent_t evFork, evPre, evA, evG0;
    cudaStreamCreateWithFlags(&side, cudaStreamNonBlocking);
    cudaEventCreateWithFlags(&evFork, cudaEventDisableTiming);
    cudaEventCreateWithFlags(&evPre,  cudaEventDisableTiming);
    cudaEventCreateWithFlags(&evA,    cudaEventDisableTiming);
    cudaEventCreateWithFlags(&evG0,   cudaEventDisableTiming);

    void* curp = nullptr;
    cudaGetSymbolAddress(&curp, g_cur);

    const int EH = NE / 2;
    const int npair = ninc / 2;
    const int nth = (npair + 1) / 2;   // 4 incidences per thread

    // main: cursors -> combined fill (critical path start)
    cudaMemsetAsync(curp, 0, NTOT * sizeof(int), 0);

    // side: transpose + x->half (hidden under memset+fill)
    cudaEventRecord(evFork, 0);
    cudaStreamWaitEvent(side, evFork, 0);
    k_transpose<<<16, 256, 0, side>>>(W);
    k_xh<<<(NN * 32 + 255) / 256, 256, 0, side>>>(x4);
    cudaEventRecord(evPre, side);

    k_fill<<<(nth + 255) / 256, 256>>>((const int2*)ni, (const int2*)ei, npair);

    // main needs x_h from side
    cudaStreamWaitEvent(0, evPre, 0);

    // sc1 halves; gemm(h0) overlaps sc1(h1) on side
    k_sc1g<<<(EH * 32 + 255) / 256, 256>>>(0, EH);
    cudaEventRecord(evA, 0);
    k_sc1g<<<((NE - EH) * 32 + 255) / 256, 256>>>(EH, NE);

    cudaStreamWaitEvent(side, evA, 0);
    k_gemm<<<(EH + 63) / 64, 256, 0, side>>>(0, EH);
    cudaEventRecord(evG0, side);

    k_gemm<<<(NE - EH + 63) / 64, 256>>>(EH, NE);

    cudaStreamWaitEvent(0, evG0, 0);
    k_sc2g<<<(NN * 32 + 255) / 256, 256>>>(bias, out4);
}

// round 12
// speedup vs baseline: 1.2215x; 1.0956x over previous
#include <cuda_runtime.h>
#include <cuda_fp16.h>

#define NN   100000           // nodes
#define NE   20000            // hyperedges
#define D    128              // feature dim
#define NTOT (NN + NE)
#define CAP_N 64              // node bucket capacity  (Poisson(8):  overflow ~0)
#define CAP_E 128             // edge bucket capacity  (Poisson(40): overflow ~0)

typedef unsigned long long u64;

// ---- scratch (static device globals; no allocation allowed) ----
__device__ int      g_cur[NTOT];              // [0,NN): node cursors ; [NN,NTOT): edge cursors
__device__ float    g_se[NE];                 // (sum invdn over edge)/d_e
__device__ float    g_ts[NN];                 // sum of se over node's edges
__device__ int      g_nlist[NN * CAP_N];      // node -> edge ids (strided buckets)
__device__ int      g_elist[NE * CAP_E];      // edge -> node ids (strided buckets)
__device__ __half2  g_xh2[NN * (D / 2)];      // x*invdn in fp16 (25.6 MB)
__device__ float4   g_eraw4[NE * (D / 4)];    // gathered edge feats fp32 (10.2 MB)
__device__ __half2  g_ewh2[NE * (D / 2)];     // e_raw @ W^T in fp16 (5.1 MB)
__device__ float4   g_wt4[D * D / 4];         // W^T (k-major)

__device__ __forceinline__ u64 dup2(float f) {
    unsigned int u = __float_as_uint(f);
    return ((u64)u << 32) | (u64)u;
}
#define FMA2(d, a, b) \
    asm("fma.rn.f32x2 %0, %1, %2, %0;" : "+l"(d) : "l"(a), "l"(b))
#define UNPACK2(lo, hi, v) \
    asm("mov.b64 {%0,%1}, %2;" : "=r"(lo), "=r"(hi) : "l"(v))

// ------------------------------------------------------------------
// combined fill: strided buckets; cursor == degree count when done.
// ------------------------------------------------------------------
__global__ void k_fill(const int2* __restrict__ ni2, const int2* __restrict__ ei2,
                       int npair) {
    int i = (blockIdx.x * blockDim.x + threadIdx.x) * 2;
    if (i >= npair) return;
    int2 na = __ldg(&ni2[i]);
    int2 ea = __ldg(&ei2[i]);
    bool two = (i + 1 < npair);
    int2 nb = two ? __ldg(&ni2[i + 1]) : make_int2(0, 0);
    int2 eb = two ? __ldg(&ei2[i + 1]) : make_int2(0, 0);

    int p0 = atomicAdd(&g_cur[NN + ea.x], 1);
    int p1 = atomicAdd(&g_cur[NN + ea.y], 1);
    int q0 = atomicAdd(&g_cur[na.x], 1);
    int q1 = atomicAdd(&g_cur[na.y], 1);
    int p2 = 0, p3 = 0, q2 = 0, q3 = 0;
    if (two) {
        p2 = atomicAdd(&g_cur[NN + eb.x], 1);
        p3 = atomicAdd(&g_cur[NN + eb.y], 1);
        q2 = atomicAdd(&g_cur[nb.x], 1);
        q3 = atomicAdd(&g_cur[nb.y], 1);
    }
    if (p0 < CAP_E) g_elist[ea.x * CAP_E + p0] = na.x;
    if (p1 < CAP_E) g_elist[ea.y * CAP_E + p1] = na.y;
    if (q0 < CAP_N) g_nlist[na.x * CAP_N + q0] = ea.x;
    if (q1 < CAP_N) g_nlist[na.y * CAP_N + q1] = ea.y;
    if (two) {
        if (p2 < CAP_E) g_elist[eb.x * CAP_E + p2] = nb.x;
        if (p3 < CAP_E) g_elist[eb.y * CAP_E + p3] = nb.y;
        if (q2 < CAP_N) g_nlist[nb.x * CAP_N + q2] = eb.x;
        if (q3 < CAP_N) g_nlist[nb.y * CAP_N + q3] = eb.y;
    }
}

// ------------------------------------------------------------------
// x (fp32) -> fp16 (unscaled; runs on side stream during fill)
// ------------------------------------------------------------------
__global__ void k_xh(const float4* __restrict__ x4) {
    int i = blockIdx.x * blockDim.x + threadIdx.x;
    if (i < NN * 32) {
        float4 v = __ldg(&x4[i]);
        __half2 h0 = __float22half2_rn(make_float2(v.x, v.y));
        __half2 h1 = __float22half2_rn(make_float2(v.z, v.w));
        uint2 pk;
        pk.x = *reinterpret_cast<unsigned int*>(&h0);
        pk.y = *reinterpret_cast<unsigned int*>(&h1);
        reinterpret_cast<uint2*>(g_xh2)[i] = pk;
    }
}

// ------------------------------------------------------------------
// in-place scale: x_h[n] *= invdn[n]  (fp32 math, single fp16 round)
// Row = 128 halves = 32 uint2  ->  iterate NN*32, node = i >> 5.
// (R10 bug was NN*16 / i>>4: scaled only half of each row.)
// ------------------------------------------------------------------
__global__ void k_xscale() {
    int i = blockIdx.x * blockDim.x + threadIdx.x;   // over NN*32 uint2 (4 halves)
    if (i >= NN * 32) return;
    int n = i >> 5;
    int c = __ldg(&g_cur[n]);
    float s = (c > 0) ? rsqrtf((float)c) : 0.f;
    uint2 pk = reinterpret_cast<uint2*>(g_xh2)[i];
    float2 f0 = __half22float2(*reinterpret_cast<__half2*>(&pk.x));
    float2 f1 = __half22float2(*reinterpret_cast<__half2*>(&pk.y));
    __half2 h0 = __float22half2_rn(make_float2(f0.x * s, f0.y * s));
    __half2 h1 = __float22half2_rn(make_float2(f1.x * s, f1.y * s));
    pk.x = *reinterpret_cast<unsigned int*>(&h0);
    pk.y = *reinterpret_cast<unsigned int*>(&h1);
    reinterpret_cast<uint2*>(g_xh2)[i] = pk;
}

// ------------------------------------------------------------------
// scalar side pass 1: se[e] = (sum_{n in e} invdn[n]) / d_e
// ------------------------------------------------------------------
__global__ void k_sev() {
    int e = blockIdx.x * blockDim.x + threadIdx.x;
    if (e >= NE) return;
    int cnt = min(__ldg(&g_cur[NN + e]), CAP_E);
    const int* lst = &g_elist[e * CAP_E];
    float s = 0.f;
    int j = 0;
    for (; j + 4 <= cnt; j += 4) {
        int i0 = __ldg(lst + j),     i1 = __ldg(lst + j + 1);
        int i2 = __ldg(lst + j + 2), i3 = __ldg(lst + j + 3);
        s += rsqrtf((float)__ldg(&g_cur[i0])) + rsqrtf((float)__ldg(&g_cur[i1]))
           + rsqrtf((float)__ldg(&g_cur[i2])) + rsqrtf((float)__ldg(&g_cur[i3]));
    }
    for (; j < cnt; ++j)
        s += rsqrtf((float)__ldg(&g_cur[__ldg(lst + j)]));
    g_se[e] = (cnt > 0) ? s * __fdividef(1.f, (float)cnt) : 0.f;
}

// ------------------------------------------------------------------
// scalar side pass 2: ts[n] = sum_{e in n} se[e]
// ------------------------------------------------------------------
__global__ void k_tsv() {
    int n = blockIdx.x * blockDim.x + threadIdx.x;
    if (n >= NN) return;
    int cnt = min(__ldg(&g_cur[n]), CAP_N);
    const int* lst = &g_nlist[n * CAP_N];
    float s = 0.f;
    int j = 0;
    for (; j + 4 <= cnt; j += 4) {
        int i0 = __ldg(lst + j),     i1 = __ldg(lst + j + 1);
        int i2 = __ldg(lst + j + 2), i3 = __ldg(lst + j + 3);
        s += __ldg(&g_se[i0]) + __ldg(&g_se[i1]) + __ldg(&g_se[i2]) + __ldg(&g_se[i3]);
    }
    for (; j < cnt; ++j)
        s += __ldg(&g_se[__ldg(lst + j)]);
    g_ts[n] = s;
}

// ------------------------------------------------------------------
// W (out,in) -> W^T (k-major)
// ------------------------------------------------------------------
__global__ void k_transpose(const float* __restrict__ W) {
    __shared__ float tile[32][33];
    int b = blockIdx.x;
    int bx = b & 3, by = b >> 2;
    int tx = threadIdx.x & 31, ty = threadIdx.x >> 5;
    float* wt = (float*)g_wt4;
#pragma unroll
    for (int j = 0; j < 32; j += 8)
        tile[ty + j][tx] = W[(by * 32 + ty + j) * D + bx * 32 + tx];
    __syncthreads();
#pragma unroll
    for (int j = 0; j < 32; j += 8)
        wt[(bx * 32 + ty + j) * D + by * 32 + tx] = tile[tx][ty + j];
}

// ------------------------------------------------------------------
// sc1: nodes -> hyperedges gather of PRE-SCALED fp16 x. warp/edge.
// Slim inner loop: idx LDG + row LDG + converts + 4 FADD only.
// ------------------------------------------------------------------
__global__ void k_sc1g(int e0, int e1) {
    int e    = e0 + ((blockIdx.x * blockDim.x + threadIdx.x) >> 5);
    int lane = threadIdx.x & 31;
    if (e >= e1) return;
    int off = e * CAP_E;
    int cnt = min(__ldg(&g_cur[NN + e]), CAP_E);
    const uint2* xh = (const uint2*)g_xh2;
    float4 a = make_float4(0.f, 0.f, 0.f, 0.f);
    int j = 0;
    for (; j + 8 <= cnt; j += 8) {
        int idx[8];
#pragma unroll
        for (int u = 0; u < 8; ++u) idx[u] = __ldg(&g_elist[off + j + u]);
        uint2 rv[8];
#pragma unroll
        for (int u = 0; u < 8; ++u) rv[u] = __ldg(&xh[idx[u] * 32 + lane]);
#pragma unroll
        for (int u = 0; u < 8; ++u) {
            float2 f0 = __half22float2(*reinterpret_cast<__half2*>(&rv[u].x));
            float2 f1 = __half22float2(*reinterpret_cast<__half2*>(&rv[u].y));
            a.x += f0.x; a.y += f0.y; a.z += f1.x; a.w += f1.y;
        }
    }
    for (; j < cnt; ++j) {
        int n = __ldg(&g_elist[off + j]);
        uint2 r = __ldg(&xh[n * 32 + lane]);
        float2 f0 = __half22float2(*reinterpret_cast<__half2*>(&r.x));
        float2 f1 = __half22float2(*reinterpret_cast<__half2*>(&r.y));
        a.x += f0.x; a.y += f0.y; a.z += f1.x; a.w += f1.y;
    }
    float ide = (cnt > 0) ? __fdividef(1.f, (float)cnt) : 0.f;
    a.x *= ide; a.y *= ide; a.z *= ide; a.w *= ide;
    g_eraw4[e * 32 + lane] = a;
}

// ------------------------------------------------------------------
// GEMM on edge-row range: g_ewh = half(g_eraw @ W^T)
// packed fp32x2 FMA; 256 thr; tile 64x128; thread 4x8
// ------------------------------------------------------------------
__global__ void __launch_bounds__(256, 2) k_gemm(int row0, int row1) {
    __shared__ u64 sW[128 * 64];
    __shared__ u64 sx[64 * 32];

    const int t  = threadIdx.x;
    const int r0 = row0 + blockIdx.x * 64;
    const int cg = t & 15;
    const int rg = t >> 4;

    {
        const ulonglong2* src = (const ulonglong2*)g_wt4;
        ulonglong2* dst = (ulonglong2*)sW;
        for (int i = t; i < 4096; i += 256) dst[i] = src[i];
    }

    u64 acc[4][4];
#pragma unroll
    for (int r = 0; r < 4; ++r)
#pragma unroll
        for (int p = 0; p < 4; ++p) acc[r][p] = 0ull;

    for (int kc = 0; kc < 4; ++kc) {
        for (int i = t; i < 512; i += 256) {
            int row = i >> 3, c4 = i & 7;
            int gr = r0 + row;
            float4 v = (gr < row1) ? g_eraw4[gr * 32 + kc * 8 + c4]
                                   : make_float4(0.f, 0.f, 0.f, 0.f);
            u64* dst = &sx[row * 32 + c4 * 4];
            dst[0] = dup2(v.x); dst[1] = dup2(v.y);
            dst[2] = dup2(v.z); dst[3] = dup2(v.w);
        }
        __syncthreads();

#pragma unroll
        for (int kk = 0; kk < 32; ++kk) {
            const ulonglong2* wp = (const ulonglong2*)&sW[(kc * 32 + kk) * 64 + cg * 4];
            ulonglong2 wa = wp[0], wb = wp[1];
            u64 w0 = wa.x, w1 = wa.y, w2 = wb.x, w3 = wb.y;
#pragma unroll
            for (int r = 0; r < 4; ++r) {
                u64 xv = sx[(rg * 4 + r) * 32 + kk];
                FMA2(acc[r][0], xv, w0);
                FMA2(acc[r][1], xv, w1);
                FMA2(acc[r][2], xv, w2);
                FMA2(acc[r][3], xv, w3);
            }
        }
        __syncthreads();
    }

#pragma unroll
    for (int r = 0; r < 4; ++r) {
        int gr = r0 + rg * 4 + r;
        if (gr < row1) {
            unsigned int lo[4], hi[4];
            UNPACK2(lo[0], hi[0], acc[r][0]); UNPACK2(lo[1], hi[1], acc[r][1]);
            UNPACK2(lo[2], hi[2], acc[r][2]); UNPACK2(lo[3], hi[3], acc[r][3]);
            uint4 pk;
            __half2 h;
            h = __float22half2_rn(make_float2(__uint_as_float(lo[0]), __uint_as_float(hi[0])));
            pk.x = *reinterpret_cast<unsigned int*>(&h);
            h = __float22half2_rn(make_float2(__uint_as_float(lo[1]), __uint_as_float(hi[1])));
            pk.y = *reinterpret_cast<unsigned int*>(&h);
            h = __float22half2_rn(make_float2(__uint_as_float(lo[2]), __uint_as_float(hi[2])));
            pk.z = *reinterpret_cast<unsigned int*>(&h);
            h = __float22half2_rn(make_float2(__uint_as_float(lo[3]), __uint_as_float(hi[3])));
            pk.w = *reinterpret_cast<unsigned int*>(&h);
            reinterpret_cast<uint4*>(g_ewh2)[gr * 16 + cg] = pk;
        }
    }
}

// ------------------------------------------------------------------
// sc2: hyperedges -> nodes gather (fp16 ew). warp per node.
// out[n] = relu( invdn[n] * ( sum_e ew[e] + ts[n] * b ) )
// ------------------------------------------------------------------
__global__ void k_sc2g(const float* __restrict__ bias, float4* __restrict__ out4) {
    int n    = (blockIdx.x * blockDim.x + threadIdx.x) >> 5;
    int lane = threadIdx.x & 31;
    if (n >= NN) return;
    int off  = n * CAP_N;
    int rawc = __ldg(&g_cur[n]);
    int cnt  = min(rawc, CAP_N);
    const uint2* ewh = (const uint2*)g_ewh2;
    float4 a = make_float4(0.f, 0.f, 0.f, 0.f);
    int j = 0;
    for (; j + 8 <= cnt; j += 8) {
        int idx[8];
#pragma unroll
        for (int u = 0; u < 8; ++u) idx[u] = __ldg(&g_nlist[off + j + u]);
        uint2 rv[8];
#pragma unroll
        for (int u = 0; u < 8; ++u) rv[u] = __ldg(&ewh[idx[u] * 32 + lane]);
#pragma unroll
        for (int u = 0; u < 8; ++u) {
            float2 f0 = __half22float2(*reinterpret_cast<__half2*>(&rv[u].x));
            float2 f1 = __half22float2(*reinterpret_cast<__half2*>(&rv[u].y));
            a.x += f0.x; a.y += f0.y; a.z += f1.x; a.w += f1.y;
        }
    }
    for (; j < cnt; ++j) {
        int e = __ldg(&g_nlist[off + j]);
        uint2 r = __ldg(&ewh[e * 32 + lane]);
        float2 f0 = __half22float2(*reinterpret_cast<__half2*>(&r.x));
        float2 f1 = __half22float2(*reinterpret_cast<__half2*>(&r.y));
        a.x += f0.x; a.y += f0.y; a.z += f1.x; a.w += f1.y;
    }
    float s  = (cnt > 0) ? rsqrtf((float)rawc) : 0.f;
    float ts = __ldg(&g_ts[n]);
    float4 bv = __ldg(&((const float4*)bias)[lane]);
    float4 o;
    o.x = fmaxf(s * (a.x + ts * bv.x), 0.f);
    o.y = fmaxf(s * (a.y + ts * bv.y), 0.f);
    o.z = fmaxf(s * (a.z + ts * bv.z), 0.f);
    o.w = fmaxf(s * (a.w + ts * bv.w), 0.f);
    out4[n * 32 + lane] = o;
}

// ------------------------------------------------------------------
extern "C" void kernel_launch(void* const* d_in, const int* in_sizes, int n_in,
                              void* d_out, int out_size) {
    const float4* x4   = (const float4*)d_in[0];
    const float*  W    = (const float*) d_in[1];
    const float*  bias = (const float*) d_in[2];
    const int*    ni   = (const int*)   d_in[3];
    const int*    ei   = (const int*)   d_in[4];
    const int     ninc = in_sizes[3];
    float4* out4 = (float4*)d_out;

    cudaStream_t side;
    cudaEvent_t evFork, evPre, evFill, evA, evG0;
    cudaStreamCreateWithFlags(&side, cudaStreamNonBlocking);
    cudaEventCreateWithFlags(&evFork, cudaEventDisableTiming);
    cudaEventCreateWithFlags(&evPre,  cudaEventDisableTiming);
    cudaEventCreateWithFlags(&evFill, cudaEventDisableTiming);
    cudaEventCreateWithFlags(&evA,    cudaEventDisableTiming);
    cudaEventCreateWithFlags(&evG0,   cudaEventDisableTiming);

    void* curp = nullptr;
    cudaGetSymbolAddress(&curp, g_cur);

    const int EH = NE / 2;
    const int npair = ninc / 2;
    const int nth = (npair + 1) / 2;   // 4 incidences per thread

    // main: cursors -> combined fill
    cudaMemsetAsync(curp, 0, NTOT * sizeof(int), 0);

    // side: transpose + x->half (hidden under memset+fill)
    cudaEventRecord(evFork, 0);
    cudaStreamWaitEvent(side, evFork, 0);
    k_transpose<<<16, 256, 0, side>>>(W);
    k_xh<<<(NN * 32 + 255) / 256, 256, 0, side>>>(x4);
    cudaEventRecord(evPre, side);

    k_fill<<<(nth + 255) / 256, 256>>>((const int2*)ni, (const int2*)ei, npair);
    cudaEventRecord(evFill, 0);

    // side: scalar se/ts passes (hidden under xscale + sc1)
    cudaStreamWaitEvent(side, evFill, 0);
    k_sev<<<(NE + 255) / 256, 256, 0, side>>>();
    k_tsv<<<(NN + 255) / 256, 256, 0, side>>>();

    // main: pre-scale x_h (needs xh from side + fill from main)
    cudaStreamWaitEvent(0, evPre, 0);
    k_xscale<<<(NN * 32 + 255) / 256, 256>>>();

    // sc1 halves; gemm(h0) overlaps sc1(h1) on side
    k_sc1g<<<(EH * 32 + 255) / 256, 256>>>(0, EH);
    cudaEventRecord(evA, 0);
    k_sc1g<<<((NE - EH) * 32 + 255) / 256, 256>>>(EH, NE);

    cudaStreamWaitEvent(side, evA, 0);
    k_gemm<<<(EH + 63) / 64, 256, 0, side>>>(0, EH);
    cudaEventRecord(evG0, side);   // implies sev+tsv done too (side ordering)

    k_gemm<<<(NE - EH + 63) / 64, 256>>>(EH, NE);

    cudaStreamWaitEvent(0, evG0, 0);
    k_sc2g<<<(NN * 32 + 255) / 256, 256>>>(bias, out4);
}